// round 5
// baseline (speedup 1.0000x reference)
#include <cuda_runtime.h>
#include <cuda_fp16.h>
#include <stdint.h>
#include <math.h>

#define Bb 2
#define Tt 2048
#define Dd 512
#define Hh 8

// ---------------- scratch (device globals) ----------------
__device__ __align__(16) float g_QZ [(size_t)Bb*Hh*Tt*Dd];   // 64 MB
__device__ __align__(16) float g_PZ [(size_t)Bb*Hh*Tt*Dd];   // 64 MB
__device__ __align__(16) float g_S  [(size_t)Bb*Hh*Tt*Tt];   // 256 MB
__device__ __align__(16) float g_Yp [(size_t)Bb*Hh*Tt*Dd];   // 64 MB
__device__ __align__(16) float g_Z  [(size_t)Bb*Tt*Dd];      // 8 MB
__device__ __align__(16) float g_M1 [(size_t)Bb*Tt*2*Dd];    // 16 MB
__device__ __align__(16) float g_Z2 [(size_t)Bb*Tt*Dd];      // 8 MB

constexpr int BM = 128, BN = 256, BK = 32, NTHR = 512;

// smem tile geometry
constexpr int A_PITCH = 80;                  // 4x16B chunks + 16B pad (ldmatrix conflict-free)
constexpr int A_TILE  = BM * A_PITCH;        // 10240 B (f16 128x32); x2 for hi+lo
constexpr int BNT_PITCH = 80;
constexpr int BNT_TILE  = BN * BNT_PITCH;    // 20480 (f16 256x32)
constexpr int BNN_PITCH = 528;               // 256 f16 = 512B + 16B pad
constexpr int BNN_TILE  = BK * BNN_PITCH;    // 16896 (f16 32x256)
constexpr int BBASE = 2 * A_TILE;            // 20480

// ---------------- PTX helpers ----------------
__device__ __forceinline__ void ldsm_x4(uint32_t (&r)[4], uint32_t addr) {
    asm volatile("ldmatrix.sync.aligned.m8n8.x4.shared.b16 {%0,%1,%2,%3}, [%4];"
                 : "=r"(r[0]), "=r"(r[1]), "=r"(r[2]), "=r"(r[3]) : "r"(addr));
}
__device__ __forceinline__ void ldsm_x4_t(uint32_t (&r)[4], uint32_t addr) {
    asm volatile("ldmatrix.sync.aligned.m8n8.x4.trans.shared.b16 {%0,%1,%2,%3}, [%4];"
                 : "=r"(r[0]), "=r"(r[1]), "=r"(r[2]), "=r"(r[3]) : "r"(addr));
}
__device__ __forceinline__ void mma16816(float (&d)[4], const uint32_t (&a)[4],
                                         uint32_t b0, uint32_t b1) {
    asm volatile("mma.sync.aligned.m16n8k16.row.col.f32.f16.f16.f32 "
                 "{%0,%1,%2,%3}, {%4,%5,%6,%7}, {%8,%9}, {%0,%1,%2,%3};"
                 : "+f"(d[0]), "+f"(d[1]), "+f"(d[2]), "+f"(d[3])
                 : "r"(a[0]), "r"(a[1]), "r"(a[2]), "r"(a[3]), "r"(b0), "r"(b1));
}

// fp32 pair -> packed f16x2 hi + f16x2 lo (lo = rounding residual)
__device__ __forceinline__ void split2h(float x0, float x1, uint32_t& hi, uint32_t& lo) {
    __half2 h = __float22half2_rn(make_float2(x0, x1));
    float2 hf = __half22float2(h);
    __half2 l = __float22half2_rn(make_float2(x0 - hf.x, x1 - hf.y));
    hi = *reinterpret_cast<uint32_t*>(&h);
    lo = *reinterpret_cast<uint32_t*>(&l);
}
__device__ __forceinline__ uint32_t pack2h(float x0, float x1) {
    __half2 h = __float22half2_rn(make_float2(x0, x1));
    return *reinterpret_cast<uint32_t*>(&h);
}
__device__ __forceinline__ void split8h(const float4& v0, const float4& v1,
                                        uint4& hi, uint4& lo) {
    split2h(v0.x, v0.y, hi.x, lo.x);
    split2h(v0.z, v0.w, hi.y, lo.y);
    split2h(v1.x, v1.y, hi.z, lo.z);
    split2h(v1.z, v1.w, hi.w, lo.w);
}
__device__ __forceinline__ uint4 pack8h(const float4& v0, const float4& v1) {
    uint4 r;
    r.x = pack2h(v0.x, v0.y); r.y = pack2h(v0.z, v0.w);
    r.z = pack2h(v1.x, v1.y); r.w = pack2h(v1.z, v1.w);
    return r;
}

// ---------------- asymmetric-split f16 GEMM via mma.sync ----------------
// C[M,N] = alpha * A[M,K] @ op(B); A split into hi+lo f16 (2 MMAs), B single f16.
// BNN=false: B is [N,K] row-major (NT). BNN=true: B is [K,N] row-major (NN).
// KLIM: kmax = rowStart + BM (causal K truncation).
// CTA tile 128x256, 16 warps, warp tile 32x64.
template <bool CAUSAL, bool RELU, bool BNN, bool KLIM>
__global__ __launch_bounds__(NTHR, 1)
void tc_gemm(const float* __restrict__ Aall, const float* __restrict__ Ball,
             float* __restrict__ Call,
             int K, int lda, int ldb, int ldc,
             int divA, int modA, size_t sA,
             int divB, int modB, size_t sB, size_t sC,
             const float* __restrict__ bias, const float* __restrict__ residual,
             float alpha)
{
    constexpr int B_TILE = BNN ? BNN_TILE : BNT_TILE;
    constexpr int BUFSZ  = 2 * A_TILE + B_TILE;

    extern __shared__ __align__(16) char smem[];
    const int tid = threadIdx.x;
    const int z = blockIdx.z;
    const float* A  = Aall + (size_t)((z / divA) % modA) * sA;
    const float* Bm = Ball + (size_t)((z / divB) % modB) * sB;
    float* C = Call + (size_t)z * sC;

    int by = blockIdx.y;
    if (CAUSAL || KLIM) by = gridDim.y - 1 - by;   // longest tiles first
    const int rowStart = by * BM;
    const int colStart = blockIdx.x * BN;
    if (CAUSAL && colStart > rowStart) return;

    const uint32_t sbase = (uint32_t)__cvta_generic_to_shared(smem);
    const int w = tid >> 5, lane = tid & 31;
    const int wm = (w & 3) * 32;      // warp M offset (4)
    const int wn = (w >> 2) * 64;     // warp N offset (4)

    const int kmax = KLIM ? (rowStart + BM) : K;
    const int nchunks = kmax / BK;

    float acc[2][8][4];
#pragma unroll
    for (int i = 0; i < 2; i++)
#pragma unroll
        for (int j = 0; j < 8; j++)
#pragma unroll
            for (int q = 0; q < 4; q++) acc[i][j][q] = 0.0f;

    // staging coordinates
    const int aRow = tid >> 2;          // 0..127
    const int aCh  = tid & 3;
    const int offA = aRow * A_PITCH + aCh * 16;

    int offB[2];
    const float* paCur = A + (size_t)(rowStart + aRow) * lda + aCh * 8;
    const float* pbCur[2];
#pragma unroll
    for (int u = 0; u < 2; u++) {
        const int iu = tid + u * 512;
        if (!BNN) {
            offB[u] = (iu >> 2) * BNT_PITCH + (iu & 3) * 16;
            pbCur[u] = Bm + (size_t)(colStart + (iu >> 2)) * ldb + (iu & 3) * 8;
        } else {
            offB[u] = (iu >> 5) * BNN_PITCH + (iu & 31) * 16;
            pbCur[u] = Bm + (size_t)(iu >> 5) * ldb + colStart + (iu & 31) * 8;
        }
    }
    const int pbStep = BNN ? BK * ldb : BK;

    // ldmatrix base addresses (buffer 0)
    const uint32_t aLd = sbase + (uint32_t)((wm + (lane & 15)) * A_PITCH + (lane >> 4) * 16);
    const uint32_t bLdNT = sbase + BBASE +
        (uint32_t)((wn + (lane & 15)) * BNT_PITCH + (lane >> 4) * 16);
    const uint32_t bLdNN = sbase + BBASE +
        (uint32_t)(((lane & 7) + ((lane & 16) >> 1)) * BNN_PITCH +
                   ((wn >> 3) + ((lane >> 3) & 1)) * 16);

    float4 pA0, pA1, pB[2][2];

    auto loadTiles = [&]() {
        pA0 = *reinterpret_cast<const float4*>(paCur);
        pA1 = *reinterpret_cast<const float4*>(paCur + 4);
        paCur += BK;
#pragma unroll
        for (int u = 0; u < 2; u++) {
            pB[u][0] = *reinterpret_cast<const float4*>(pbCur[u]);
            pB[u][1] = *reinterpret_cast<const float4*>(pbCur[u] + 4);
            pbCur[u] += pbStep;
        }
    };
    auto storeTiles = [&](int buf) {
        char* base = smem + buf * BUFSZ;
        uint4 hi, lo;
        split8h(pA0, pA1, hi, lo);
        *reinterpret_cast<uint4*>(base + offA) = hi;
        *reinterpret_cast<uint4*>(base + A_TILE + offA) = lo;
#pragma unroll
        for (int u = 0; u < 2; u++)
            *reinterpret_cast<uint4*>(base + BBASE + offB[u]) = pack8h(pB[u][0], pB[u][1]);
    };

    loadTiles();
    storeTiles(0);
    __syncthreads();

    for (int c = 0; c < nchunks; c++) {
        const uint32_t bo = (uint32_t)((c & 1) * BUFSZ);
        if (c + 1 < nchunks) loadTiles();

#pragma unroll
        for (int ks = 0; ks < 2; ks++) {
            uint32_t aHi[2][4], aLo[2][4], bF[4][4];
#pragma unroll
            for (int mi = 0; mi < 2; mi++) {
                ldsm_x4(aHi[mi], aLd + bo + (uint32_t)(mi * 16 * A_PITCH + ks * 32));
                ldsm_x4(aLo[mi], aLd + bo + (uint32_t)(A_TILE + mi * 16 * A_PITCH + ks * 32));
            }
#pragma unroll
            for (int q = 0; q < 4; q++) {
                if (!BNN)
                    ldsm_x4(bF[q], bLdNT + bo + (uint32_t)(q * 16 * BNT_PITCH + ks * 32));
                else
                    ldsm_x4_t(bF[q], bLdNN + bo + (uint32_t)(q * 32 + ks * 16 * BNN_PITCH));
            }
            // hi sweep, then lo sweep: same-acc reuse distance = 16 MMAs
#pragma unroll
            for (int mi = 0; mi < 2; mi++)
#pragma unroll
                for (int ni = 0; ni < 8; ni++) {
                    const int q = ni >> 1, s = ni & 1;
                    mma16816(acc[mi][ni], aHi[mi], bF[q][s], bF[q][s + 2]);
                }
#pragma unroll
            for (int mi = 0; mi < 2; mi++)
#pragma unroll
                for (int ni = 0; ni < 8; ni++) {
                    const int q = ni >> 1, s = ni & 1;
                    mma16816(acc[mi][ni], aLo[mi], bF[q][s], bF[q][s + 2]);
                }
        }

        if (c + 1 < nchunks) storeTiles((c + 1) & 1);
        __syncthreads();
    }

    // ---------------- epilogue ----------------
    const int r0 = rowStart + wm + (lane >> 2);
    const int c0 = colStart + wn + (lane & 3) * 2;
#pragma unroll
    for (int mi = 0; mi < 2; mi++) {
        const int r = r0 + mi * 16;
#pragma unroll
        for (int ni = 0; ni < 8; ni++) {
            const int c = c0 + ni * 8;
            float v00 = acc[mi][ni][0] * alpha, v01 = acc[mi][ni][1] * alpha;
            float v10 = acc[mi][ni][2] * alpha, v11 = acc[mi][ni][3] * alpha;
            if (CAUSAL) {
                if (c > r)         v00 = 0.0f;
                if (c + 1 > r)     v01 = 0.0f;
                if (c > r + 8)     v10 = 0.0f;
                if (c + 1 > r + 8) v11 = 0.0f;
            }
            if (bias) {
                const float bv0 = bias[c], bv1 = bias[c + 1];
                v00 += bv0; v01 += bv1; v10 += bv0; v11 += bv1;
            }
            if (RELU) {
                v00 = fmaxf(v00, 0.0f); v01 = fmaxf(v01, 0.0f);
                v10 = fmaxf(v10, 0.0f); v11 = fmaxf(v11, 0.0f);
            }
            if (residual) {
                const float2 q0 = *reinterpret_cast<const float2*>(residual + (size_t)r * ldc + c);
                const float2 q1 = *reinterpret_cast<const float2*>(residual + (size_t)(r + 8) * ldc + c);
                v00 += q0.x; v01 += q0.y; v10 += q1.x; v11 += q1.y;
            }
            *reinterpret_cast<float2*>(C + (size_t)r * ldc + c)       = make_float2(v00, v01);
            *reinterpret_cast<float2*>(C + (size_t)(r + 8) * ldc + c) = make_float2(v10, v11);
        }
    }
}

// ---------------- fused head-mean + residual + LayerNorm ----------------
__global__ __launch_bounds__(128)
void ln_reduce(const float* __restrict__ Yp, const float* __restrict__ X,
               const float* __restrict__ gamma, const float* __restrict__ beta,
               float* __restrict__ Z)
{
    const int row = blockIdx.x;          // b*T + t
    const int b = row >> 11, t = row & (Tt - 1);
    const int tid = threadIdx.x;
    const int c0 = tid * 4;

    float4 acc = make_float4(0.f, 0.f, 0.f, 0.f);
#pragma unroll
    for (int h = 0; h < Hh; h++) {
        const float4 y4 = *reinterpret_cast<const float4*>(
            Yp + ((size_t)(b * Hh + h) * Tt + t) * Dd + c0);
        acc.x += y4.x; acc.y += y4.y; acc.z += y4.z; acc.w += y4.w;
    }
    const float4 x4 = *reinterpret_cast<const float4*>(X + (size_t)row * Dd + c0);
    float v[4] = { acc.x * 0.125f + x4.x, acc.y * 0.125f + x4.y,
                   acc.z * 0.125f + x4.z, acc.w * 0.125f + x4.w };

    float s  = v[0] + v[1] + v[2] + v[3];
    float sq = v[0]*v[0] + v[1]*v[1] + v[2]*v[2] + v[3]*v[3];
#pragma unroll
    for (int o = 16; o > 0; o >>= 1) {
        s  += __shfl_xor_sync(0xffffffffu, s, o);
        sq += __shfl_xor_sync(0xffffffffu, sq, o);
    }
    __shared__ float sh[8];
    __shared__ float s_mean, s_rstd;
    const int wq = tid >> 5, lane = tid & 31;
    if (lane == 0) { sh[wq] = s; sh[4 + wq] = sq; }
    __syncthreads();
    if (tid == 0) {
        float ts = sh[0] + sh[1] + sh[2] + sh[3];
        float tq = sh[4] + sh[5] + sh[6] + sh[7];
        float mean = ts / (float)Dd;
        float var  = tq / (float)Dd - mean * mean;
        s_mean = mean; s_rstd = rsqrtf(var + 1e-5f);
    }
    __syncthreads();
    const float mean = s_mean, rstd = s_rstd;
#pragma unroll
    for (int i = 0; i < 4; i++) {
        const int c = c0 + i;
        Z[(size_t)row * Dd + c] = (v[i] - mean) * rstd * gamma[c] + beta[c];
    }
}

// ---------------- launcher ----------------
extern "C" void kernel_launch(void* const* d_in, const int* in_sizes, int n_in,
                              void* d_out, int out_size)
{
    (void)in_sizes; (void)n_in; (void)out_size;
    const float* x     = (const float*)d_in[0];
    const float* P     = (const float*)d_in[1];
    const float* Q     = (const float*)d_in[2];
    const float* gamma = (const float*)d_in[3];
    const float* beta  = (const float*)d_in[4];
    const float* W1    = (const float*)d_in[5];
    const float* b1    = (const float*)d_in[6];
    const float* W2    = (const float*)d_in[7];
    const float* b2    = (const float*)d_in[8];
    const float* Wp    = (const float*)d_in[9];
    const float* bp    = (const float*)d_in[10];
    float* out = (float*)d_out;

    float *QZ, *PZ, *S, *Yp, *Z, *M1, *Z2;
    cudaGetSymbolAddress((void**)&QZ, g_QZ);
    cudaGetSymbolAddress((void**)&PZ, g_PZ);
    cudaGetSymbolAddress((void**)&S,  g_S);
    cudaGetSymbolAddress((void**)&Yp, g_Yp);
    cudaGetSymbolAddress((void**)&Z,  g_Z);
    cudaGetSymbolAddress((void**)&M1, g_M1);
    cudaGetSymbolAddress((void**)&Z2, g_Z2);

    constexpr int SM_NT = 2 * (2 * A_TILE + BNT_TILE);   // 81920
    constexpr int SM_NN = 2 * (2 * A_TILE + BNN_TILE);   // 74752

    static bool attr_done = false;
    if (!attr_done) {
        cudaFuncSetAttribute(tc_gemm<false,false,false,false>,
                             cudaFuncAttributeMaxDynamicSharedMemorySize, SM_NT);
        cudaFuncSetAttribute(tc_gemm<true,false,false,false>,
                             cudaFuncAttributeMaxDynamicSharedMemorySize, SM_NT);
        cudaFuncSetAttribute(tc_gemm<false,false,true,true>,
                             cudaFuncAttributeMaxDynamicSharedMemorySize, SM_NN);
        cudaFuncSetAttribute(tc_gemm<false,true,false,false>,
                             cudaFuncAttributeMaxDynamicSharedMemorySize, SM_NT);
        attr_done = true;
    }

    const dim3 blk(NTHR);
    const float inv_sqrt_d = 1.0f / sqrtf((float)Dd);

    // 1) QZ[z=b*8+h] = x[b] @ Q[h]^T   [T x D]
    tc_gemm<false,false,false,false><<<dim3(2, 16, 16), blk, SM_NT>>>(
        x, Q, QZ, Dd, Dd, Dd, Dd,
        Hh, Bb, (size_t)Tt * Dd,
        1,  Hh, (size_t)Dd * Dd,
        (size_t)Tt * Dd, nullptr, nullptr, 1.0f);

    // 2) PZ[z] = x[b] @ P[h]^T   [T x D]
    tc_gemm<false,false,false,false><<<dim3(2, 16, 16), blk, SM_NT>>>(
        x, P, PZ, Dd, Dd, Dd, Dd,
        Hh, Bb, (size_t)Tt * Dd,
        1,  Hh, (size_t)Dd * Dd,
        (size_t)Tt * Dd, nullptr, nullptr, 1.0f);

    // 3) S[z] = tril(QZ[z] @ x[b]^T) / sqrt(D)   [T x T]
    tc_gemm<true,false,false,false><<<dim3(8, 16, 16), blk, SM_NT>>>(
        QZ, x, S, Dd, Dd, Dd, Tt,
        1, Bb * Hh, (size_t)Tt * Dd,
        Hh, Bb,     (size_t)Tt * Dd,
        (size_t)Tt * Tt, nullptr, nullptr, inv_sqrt_d);

    // 4) Yp[z] = S[z] @ PZ[z]   [T x D], NN, causal K-limit
    tc_gemm<false,false,true,true><<<dim3(2, 16, 16), blk, SM_NN>>>(
        S, PZ, Yp, Tt, Tt, Dd, Dd,
        1, Bb * Hh, (size_t)Tt * Tt,
        1, Bb * Hh, (size_t)Tt * Dd,
        (size_t)Tt * Dd, nullptr, nullptr, 1.0f);

    // 5) Z = LayerNorm(mean_h(Yp) + x)
    ln_reduce<<<Bb * Tt, 128>>>(Yp, x, gamma, beta, Z);

    // 6) M1 = relu(Z @ W1^T + b1)   [4096 x 1024]
    tc_gemm<false,true,false,false><<<dim3(4, 32, 1), blk, SM_NT>>>(
        Z, W1, M1, Dd, Dd, Dd, 2 * Dd,
        1, 1, 0, 1, 1, 0, 0, b1, nullptr, 1.0f);

    // 7) Z2 = Z + (M1 @ W2^T + b2)  [4096 x 512]
    tc_gemm<false,false,false,false><<<dim3(2, 32, 1), blk, SM_NT>>>(
        M1, W2, Z2, 2 * Dd, 2 * Dd, 2 * Dd, Dd,
        1, 1, 0, 1, 1, 0, 0, b2, Z, 1.0f);

    // 8) out = Z2 @ Wp^T + bp       [4096 x 512]
    tc_gemm<false,false,false,false><<<dim3(2, 32, 1), blk, SM_NT>>>(
        Z2, Wp, out, Dd, Dd, Dd, Dd,
        1, 1, 0, 1, 1, 0, 0, bp, nullptr, 1.0f);
}

// round 7
// speedup vs baseline: 1.2282x; 1.2282x over previous
#include <cuda_runtime.h>
#include <cuda_fp16.h>
#include <stdint.h>
#include <math.h>

#define Bb 2
#define Tt 2048
#define Dd 512
#define Hh 8

// ---------------- scratch (device globals) ----------------
// f16 operand planes (hi = rn(x), lo = rn(x - hi))
__device__ __align__(16) __half g_xhi [(size_t)Bb*Tt*Dd];
__device__ __align__(16) __half g_xlo [(size_t)Bb*Tt*Dd];
__device__ __align__(16) __half g_Qh  [(size_t)Hh*Dd*Dd];
__device__ __align__(16) __half g_Ph  [(size_t)Hh*Dd*Dd];
__device__ __align__(16) __half g_W1h [(size_t)2*Dd*Dd];
__device__ __align__(16) __half g_W2h [(size_t)Dd*2*Dd];
__device__ __align__(16) __half g_Wph [(size_t)Dd*Dd];
__device__ __align__(16) __half g_QZhi[(size_t)Bb*Hh*Tt*Dd];
__device__ __align__(16) __half g_QZlo[(size_t)Bb*Hh*Tt*Dd];
__device__ __align__(16) __half g_PZhi[(size_t)Bb*Hh*Tt*Dd];
__device__ __align__(16) __half g_Shi [(size_t)Bb*Hh*Tt*Tt];   // 128 MB
__device__ __align__(16) __half g_Slo [(size_t)Bb*Hh*Tt*Tt];   // 128 MB
__device__ __align__(16) float  g_Yp  [(size_t)Bb*Hh*Tt*Dd];   // 64 MB
__device__ __align__(16) float  g_Z   [(size_t)Bb*Tt*Dd];
__device__ __align__(16) __half g_Zhi [(size_t)Bb*Tt*Dd];
__device__ __align__(16) __half g_Zlo [(size_t)Bb*Tt*Dd];
__device__ __align__(16) __half g_M1hi[(size_t)Bb*Tt*2*Dd];
__device__ __align__(16) __half g_M1lo[(size_t)Bb*Tt*2*Dd];
__device__ __align__(16) __half g_Z2hi[(size_t)Bb*Tt*Dd];
__device__ __align__(16) __half g_Z2lo[(size_t)Bb*Tt*Dd];

constexpr int BM = 128, BN = 128, BK = 32, NTHR = 512;

// smem tile geometry (f16)
constexpr int A_PITCH = 80;                  // 32 halves (64B) + 16B pad
constexpr int A_TILE  = BM * A_PITCH;        // 10240
constexpr int BNT_PITCH = 80;
constexpr int BNT_TILE  = BN * BNT_PITCH;    // 10240
constexpr int BNN_PITCH = 272;               // 128 halves (256B) + 16B pad
constexpr int BNN_TILE  = BK * BNN_PITCH;    // 8704
constexpr int BBASE = 2 * A_TILE;

// ---------------- PTX helpers ----------------
__device__ __forceinline__ void ldsm_x4(uint32_t (&r)[4], uint32_t addr) {
    asm volatile("ldmatrix.sync.aligned.m8n8.x4.shared.b16 {%0,%1,%2,%3}, [%4];"
                 : "=r"(r[0]), "=r"(r[1]), "=r"(r[2]), "=r"(r[3]) : "r"(addr));
}
__device__ __forceinline__ void ldsm_x4_t(uint32_t (&r)[4], uint32_t addr) {
    asm volatile("ldmatrix.sync.aligned.m8n8.x4.trans.shared.b16 {%0,%1,%2,%3}, [%4];"
                 : "=r"(r[0]), "=r"(r[1]), "=r"(r[2]), "=r"(r[3]) : "r"(addr));
}
__device__ __forceinline__ void mma16816(float (&d)[4], const uint32_t (&a)[4],
                                         uint32_t b0, uint32_t b1) {
    asm volatile("mma.sync.aligned.m16n8k16.row.col.f32.f16.f16.f32 "
                 "{%0,%1,%2,%3}, {%4,%5,%6,%7}, {%8,%9}, {%0,%1,%2,%3};"
                 : "+f"(d[0]), "+f"(d[1]), "+f"(d[2]), "+f"(d[3])
                 : "r"(a[0]), "r"(a[1]), "r"(a[2]), "r"(a[3]), "r"(b0), "r"(b1));
}
__device__ __forceinline__ void split2h(float x0, float x1, uint32_t& hi, uint32_t& lo) {
    __half2 h = __float22half2_rn(make_float2(x0, x1));
    float2 hf = __half22float2(h);
    __half2 l = __float22half2_rn(make_float2(x0 - hf.x, x1 - hf.y));
    hi = *reinterpret_cast<uint32_t*>(&h);
    lo = *reinterpret_cast<uint32_t*>(&l);
}

// ---------------- asymmetric-split f16 GEMM via mma.sync ----------------
// C = alpha * A @ op(B); A = hi+lo f16 planes (2 MMAs), B = hi f16 plane.
// BNN=false: B is [N,K] (NT). BNN=true: B is [K,N] (NN).
// KLIM: kmax = rowStart + BM. OMODE: 0 = fp32 C, 1 = hi+lo planes, 3 = hi plane only.
template <bool CAUSAL, bool RELU, bool BNN, bool KLIM, int OMODE>
__global__ __launch_bounds__(NTHR, 1)
void tc_gemm(const __half* __restrict__ AhiAll, const __half* __restrict__ AloAll,
             const __half* __restrict__ BhiAll,
             float* __restrict__ Call, __half* __restrict__ ChiAll, __half* __restrict__ CloAll,
             int K, int lda, int ldb, int ldc,
             int divA, int modA, size_t sA,
             int divB, int modB, size_t sB, size_t sC,
             const float* __restrict__ bias, const float* __restrict__ residual,
             float alpha)
{
    constexpr int B_TILE = BNN ? BNN_TILE : BNT_TILE;
    constexpr int BUFSZ  = 2 * A_TILE + B_TILE;

    extern __shared__ __align__(16) char smem[];
    const int tid = threadIdx.x;
    const int z = blockIdx.z;
    const size_t offAz = (size_t)((z / divA) % modA) * sA;
    const __half* Ahi = AhiAll + offAz;
    const __half* Alo = AloAll + offAz;
    const __half* Bhi = BhiAll + (size_t)((z / divB) % modB) * sB;

    int by = blockIdx.y;
    if (CAUSAL || KLIM) by = gridDim.y - 1 - by;   // longest tiles first
    const int rowStart = by * BM;
    const int colStart = blockIdx.x * BN;
    if (CAUSAL && colStart > rowStart) return;

    const uint32_t sbase = (uint32_t)__cvta_generic_to_shared(smem);
    const int w = tid >> 5, lane = tid & 31;
    const int wm = (w & 3) * 32;      // warp M offset
    const int wn = (w >> 2) * 32;     // warp N offset

    const int kmax = KLIM ? (rowStart + BM) : K;
    const int nchunks = kmax / BK;

    float acc[2][4][4];
#pragma unroll
    for (int i = 0; i < 2; i++)
#pragma unroll
        for (int j = 0; j < 4; j++)
#pragma unroll
            for (int q = 0; q < 4; q++) acc[i][j][q] = 0.0f;

    // per-thread staging coordinates (each thread moves 16B = 8 halves per tile)
    const int aRow = tid >> 2;          // 0..127
    const int aCh  = tid & 3;
    const int offA = aRow * A_PITCH + aCh * 16;
    const int bRowNN = tid >> 4;        // 0..31
    const int bChNN  = tid & 15;
    const int offB = BNN ? (bRowNN * BNN_PITCH + bChNN * 16)
                         : (aRow * BNT_PITCH + aCh * 16);

    const __half* paHi = Ahi + (size_t)(rowStart + aRow) * lda + aCh * 8;
    const __half* paLo = Alo + (size_t)(rowStart + aRow) * lda + aCh * 8;
    const __half* pb = BNN
        ? Bhi + (size_t)bRowNN * ldb + colStart + bChNN * 8
        : Bhi + (size_t)(colStart + aRow) * ldb + aCh * 8;
    const int pbStep = BNN ? BK * ldb : BK;

    // ldmatrix base addresses (buffer 0)
    const uint32_t aLd = sbase + (uint32_t)((wm + (lane & 15)) * A_PITCH + (lane >> 4) * 16);
    const uint32_t bLdNT = sbase + BBASE +
        (uint32_t)((wn + (lane & 15)) * BNT_PITCH + (lane >> 4) * 16);
    const uint32_t bLdNN = sbase + BBASE +
        (uint32_t)(((lane & 7) + ((lane & 16) >> 1)) * BNN_PITCH +
                   ((wn >> 3) + ((lane >> 3) & 1)) * 16);

    uint4 rAhi, rAlo, rBt;

    auto loadTiles = [&]() {
        rAhi = *reinterpret_cast<const uint4*>(paHi);
        rAlo = *reinterpret_cast<const uint4*>(paLo);
        rBt  = *reinterpret_cast<const uint4*>(pb);
        paHi += BK; paLo += BK; pb += pbStep;
    };
    auto storeTiles = [&](int buf) {
        char* base = smem + buf * BUFSZ;
        *reinterpret_cast<uint4*>(base + offA) = rAhi;
        *reinterpret_cast<uint4*>(base + A_TILE + offA) = rAlo;
        *reinterpret_cast<uint4*>(base + BBASE + offB) = rBt;
    };

    loadTiles();
    storeTiles(0);
    __syncthreads();

    for (int c = 0; c < nchunks; c++) {
        const uint32_t bo = (uint32_t)((c & 1) * BUFSZ);
        if (c + 1 < nchunks) loadTiles();

#pragma unroll
        for (int ks = 0; ks < 2; ks++) {
            uint32_t aHi[2][4], aLo[2][4], bF[2][4];
#pragma unroll
            for (int mi = 0; mi < 2; mi++) {
                ldsm_x4(aHi[mi], aLd + bo + (uint32_t)(mi * 16 * A_PITCH + ks * 32));
                ldsm_x4(aLo[mi], aLd + bo + (uint32_t)(A_TILE + mi * 16 * A_PITCH + ks * 32));
            }
#pragma unroll
            for (int p = 0; p < 2; p++) {
                if (!BNN)
                    ldsm_x4(bF[p], bLdNT + bo + (uint32_t)(p * 16 * BNT_PITCH + ks * 32));
                else
                    ldsm_x4_t(bF[p], bLdNN + bo + (uint32_t)(p * 32 + ks * 16 * BNN_PITCH));
            }
            // hi sweep then lo sweep: same-acc reuse distance = 8 MMAs
#pragma unroll
            for (int mi = 0; mi < 2; mi++)
#pragma unroll
                for (int ni = 0; ni < 4; ni++) {
                    const int p = ni >> 1, s = ni & 1;
                    mma16816(acc[mi][ni], aHi[mi], bF[p][s], bF[p][s + 2]);
                }
#pragma unroll
            for (int mi = 0; mi < 2; mi++)
#pragma unroll
                for (int ni = 0; ni < 4; ni++) {
                    const int p = ni >> 1, s = ni & 1;
                    mma16816(acc[mi][ni], aLo[mi], bF[p][s], bF[p][s + 2]);
                }
        }

        if (c + 1 < nchunks) storeTiles((c + 1) & 1);
        __syncthreads();
    }

    // ---------------- epilogue ----------------
    float* C = (OMODE == 0) ? Call + (size_t)z * sC : nullptr;
    __half* Chi = (OMODE == 1 || OMODE == 3) ? ChiAll + (size_t)z * sC : nullptr;
    __half* Clo = (OMODE == 1) ? CloAll + (size_t)z * sC : nullptr;

    const int r0 = rowStart + wm + (lane >> 2);
    const int c0 = colStart + wn + (lane & 3) * 2;
#pragma unroll
    for (int mi = 0; mi < 2; mi++) {
        const int r = r0 + mi * 16;
#pragma unroll
        for (int ni = 0; ni < 4; ni++) {
            const int c = c0 + ni * 8;
            float v00 = acc[mi][ni][0] * alpha, v01 = acc[mi][ni][1] * alpha;
            float v10 = acc[mi][ni][2] * alpha, v11 = acc[mi][ni][3] * alpha;
            if (CAUSAL) {
                if (c > r)         v00 = 0.0f;
                if (c + 1 > r)     v01 = 0.0f;
                if (c > r + 8)     v10 = 0.0f;
                if (c + 1 > r + 8) v11 = 0.0f;
            }
            if (bias) {
                const float bv0 = bias[c], bv1 = bias[c + 1];
                v00 += bv0; v01 += bv1; v10 += bv0; v11 += bv1;
            }
            if (RELU) {
                v00 = fmaxf(v00, 0.0f); v01 = fmaxf(v01, 0.0f);
                v10 = fmaxf(v10, 0.0f); v11 = fmaxf(v11, 0.0f);
            }
            if (residual) {
                const float2 q0 = *reinterpret_cast<const float2*>(residual + (size_t)r * ldc + c);
                const float2 q1 = *reinterpret_cast<const float2*>(residual + (size_t)(r + 8) * ldc + c);
                v00 += q0.x; v01 += q0.y; v10 += q1.x; v11 += q1.y;
            }
            if (OMODE == 0) {
                *reinterpret_cast<float2*>(C + (size_t)r * ldc + c)       = make_float2(v00, v01);
                *reinterpret_cast<float2*>(C + (size_t)(r + 8) * ldc + c) = make_float2(v10, v11);
            } else {
                uint32_t h0, l0, h1, l1;
                split2h(v00, v01, h0, l0);
                split2h(v10, v11, h1, l1);
                *reinterpret_cast<uint32_t*>(Chi + (size_t)r * ldc + c)       = h0;
                *reinterpret_cast<uint32_t*>(Chi + (size_t)(r + 8) * ldc + c) = h1;
                if (OMODE == 1) {
                    *reinterpret_cast<uint32_t*>(Clo + (size_t)r * ldc + c)       = l0;
                    *reinterpret_cast<uint32_t*>(Clo + (size_t)(r + 8) * ldc + c) = l1;
                }
            }
        }
    }
}

// ---------------- converters ----------------
__global__ __launch_bounds__(256)
void split_f32(const float* __restrict__ src, __half* __restrict__ hi,
               __half* __restrict__ lo, int n4)
{
    const int i = blockIdx.x * 256 + threadIdx.x;
    if (i >= n4) return;
    const float4 v = reinterpret_cast<const float4*>(src)[i];
    uint32_t h0, l0, h1, l1;
    split2h(v.x, v.y, h0, l0);
    split2h(v.z, v.w, h1, l1);
    reinterpret_cast<uint2*>(hi)[i] = make_uint2(h0, h1);
    reinterpret_cast<uint2*>(lo)[i] = make_uint2(l0, l1);
}
__global__ __launch_bounds__(256)
void tohalf_f32(const float* __restrict__ src, __half* __restrict__ hi, int n4)
{
    const int i = blockIdx.x * 256 + threadIdx.x;
    if (i >= n4) return;
    const float4 v = reinterpret_cast<const float4*>(src)[i];
    __half2 a = __float22half2_rn(make_float2(v.x, v.y));
    __half2 b = __float22half2_rn(make_float2(v.z, v.w));
    reinterpret_cast<uint2*>(hi)[i] =
        make_uint2(*reinterpret_cast<uint32_t*>(&a), *reinterpret_cast<uint32_t*>(&b));
}

// ---------------- fused head-mean + residual + LayerNorm (+ split planes) ----------------
__global__ __launch_bounds__(128)
void ln_reduce(const float* __restrict__ Yp, const float* __restrict__ X,
               const float* __restrict__ gamma, const float* __restrict__ beta,
               float* __restrict__ Z, __half* __restrict__ Zhi, __half* __restrict__ Zlo)
{
    const int row = blockIdx.x;          // b*T + t
    const int b = row >> 11, t = row & (Tt - 1);
    const int tid = threadIdx.x;
    const int c0 = tid * 4;

    float4 acc = make_float4(0.f, 0.f, 0.f, 0.f);
#pragma unroll
    for (int h = 0; h < Hh; h++) {
        const float4 y4 = *reinterpret_cast<const float4*>(
            Yp + ((size_t)(b * Hh + h) * Tt + t) * Dd + c0);
        acc.x += y4.x; acc.y += y4.y; acc.z += y4.z; acc.w += y4.w;
    }
    const float4 x4 = *reinterpret_cast<const float4*>(X + (size_t)row * Dd + c0);
    float v[4] = { acc.x * 0.125f + x4.x, acc.y * 0.125f + x4.y,
                   acc.z * 0.125f + x4.z, acc.w * 0.125f + x4.w };

    float s  = v[0] + v[1] + v[2] + v[3];
    float sq = v[0]*v[0] + v[1]*v[1] + v[2]*v[2] + v[3]*v[3];
#pragma unroll
    for (int o = 16; o > 0; o >>= 1) {
        s  += __shfl_xor_sync(0xffffffffu, s, o);
        sq += __shfl_xor_sync(0xffffffffu, sq, o);
    }
    __shared__ float sh[8];
    __shared__ float s_mean, s_rstd;
    const int wq = tid >> 5, lane = tid & 31;
    if (lane == 0) { sh[wq] = s; sh[4 + wq] = sq; }
    __syncthreads();
    if (tid == 0) {
        float ts = sh[0] + sh[1] + sh[2] + sh[3];
        float tq = sh[4] + sh[5] + sh[6] + sh[7];
        float mean = ts / (float)Dd;
        float var  = tq / (float)Dd - mean * mean;
        s_mean = mean; s_rstd = rsqrtf(var + 1e-5f);
    }
    __syncthreads();
    const float mean = s_mean, rstd = s_rstd;
    float o[4];
#pragma unroll
    for (int i = 0; i < 4; i++) {
        const int c = c0 + i;
        o[i] = (v[i] - mean) * rstd * gamma[c] + beta[c];
    }
    const size_t off = (size_t)row * Dd + c0;
    *reinterpret_cast<float4*>(Z + off) = make_float4(o[0], o[1], o[2], o[3]);
    uint32_t h0, l0, h1, l1;
    split2h(o[0], o[1], h0, l0);
    split2h(o[2], o[3], h1, l1);
    *reinterpret_cast<uint2*>(Zhi + off) = make_uint2(h0, h1);
    *reinterpret_cast<uint2*>(Zlo + off) = make_uint2(l0, l1);
}

// ---------------- launcher ----------------
extern "C" void kernel_launch(void* const* d_in, const int* in_sizes, int n_in,
                              void* d_out, int out_size)
{
    (void)in_sizes; (void)n_in; (void)out_size;
    const float* x     = (const float*)d_in[0];
    const float* P     = (const float*)d_in[1];
    const float* Q     = (const float*)d_in[2];
    const float* gamma = (const float*)d_in[3];
    const float* beta  = (const float*)d_in[4];
    const float* W1    = (const float*)d_in[5];
    const float* b1    = (const float*)d_in[6];
    const float* W2    = (const float*)d_in[7];
    const float* b2    = (const float*)d_in[8];
    const float* Wp    = (const float*)d_in[9];
    const float* bp    = (const float*)d_in[10];
    float* out = (float*)d_out;

    __half *xhi, *xlo, *Qh, *Ph, *W1h, *W2h, *Wph;
    __half *QZhi, *QZlo, *PZhi, *Shi, *Slo, *Zhi, *Zlo, *M1hi, *M1lo, *Z2hi, *Z2lo;
    float *Yp, *Z;
    cudaGetSymbolAddress((void**)&xhi,  g_xhi);
    cudaGetSymbolAddress((void**)&xlo,  g_xlo);
    cudaGetSymbolAddress((void**)&Qh,   g_Qh);
    cudaGetSymbolAddress((void**)&Ph,   g_Ph);
    cudaGetSymbolAddress((void**)&W1h,  g_W1h);
    cudaGetSymbolAddress((void**)&W2h,  g_W2h);
    cudaGetSymbolAddress((void**)&Wph,  g_Wph);
    cudaGetSymbolAddress((void**)&QZhi, g_QZhi);
    cudaGetSymbolAddress((void**)&QZlo, g_QZlo);
    cudaGetSymbolAddress((void**)&PZhi, g_PZhi);
    cudaGetSymbolAddress((void**)&Shi,  g_Shi);
    cudaGetSymbolAddress((void**)&Slo,  g_Slo);
    cudaGetSymbolAddress((void**)&Yp,   g_Yp);
    cudaGetSymbolAddress((void**)&Z,    g_Z);
    cudaGetSymbolAddress((void**)&Zhi,  g_Zhi);
    cudaGetSymbolAddress((void**)&Zlo,  g_Zlo);
    cudaGetSymbolAddress((void**)&M1hi, g_M1hi);
    cudaGetSymbolAddress((void**)&M1lo, g_M1lo);
    cudaGetSymbolAddress((void**)&Z2hi, g_Z2hi);
    cudaGetSymbolAddress((void**)&Z2lo, g_Z2lo);

    constexpr int SM_NT = 2 * (2 * A_TILE + BNT_TILE);   // 61440
    constexpr int SM_NN = 2 * (2 * A_TILE + BNN_TILE);   // 58368

    static bool attr_done = false;
    if (!attr_done) {
        cudaFuncSetAttribute(tc_gemm<false,false,false,false,1>,
                             cudaFuncAttributeMaxDynamicSharedMemorySize, SM_NT);
        cudaFuncSetAttribute(tc_gemm<false,false,false,false,3>,
                             cudaFuncAttributeMaxDynamicSharedMemorySize, SM_NT);
        cudaFuncSetAttribute(tc_gemm<false,false,false,false,0>,
                             cudaFuncAttributeMaxDynamicSharedMemorySize, SM_NT);
        cudaFuncSetAttribute(tc_gemm<true,false,false,false,1>,
                             cudaFuncAttributeMaxDynamicSharedMemorySize, SM_NT);
        cudaFuncSetAttribute(tc_gemm<false,false,true,true,0>,
                             cudaFuncAttributeMaxDynamicSharedMemorySize, SM_NN);
        cudaFuncSetAttribute(tc_gemm<false,true,false,false,1>,
                             cudaFuncAttributeMaxDynamicSharedMemorySize, SM_NT);
        attr_done = true;
    }

    const dim3 blk(NTHR);
    const float inv_sqrt_d = 1.0f / sqrtf((float)Dd);

    // 0) pre-split inputs / weights
    split_f32<<<(Bb*Tt*Dd/4 + 255)/256, 256>>>(x, xhi, xlo, Bb*Tt*Dd/4);
    tohalf_f32<<<(Hh*Dd*Dd/4 + 255)/256, 256>>>(Q, Qh, Hh*Dd*Dd/4);
    tohalf_f32<<<(Hh*Dd*Dd/4 + 255)/256, 256>>>(P, Ph, Hh*Dd*Dd/4);
    tohalf_f32<<<(2*Dd*Dd/4 + 255)/256, 256>>>(W1, W1h, 2*Dd*Dd/4);
    tohalf_f32<<<(2*Dd*Dd/4 + 255)/256, 256>>>(W2, W2h, 2*Dd*Dd/4);
    tohalf_f32<<<(Dd*Dd/4 + 255)/256, 256>>>(Wp, Wph, Dd*Dd/4);

    // 1) QZ[z=b*8+h] = x[b] @ Q[h]^T -> split planes
    tc_gemm<false,false,false,false,1><<<dim3(4, 16, 16), blk, SM_NT>>>(
        xhi, xlo, Qh, nullptr, QZhi, QZlo,
        Dd, Dd, Dd, Dd,
        Hh, Bb, (size_t)Tt * Dd,
        1,  Hh, (size_t)Dd * Dd,
        (size_t)Tt * Dd, nullptr, nullptr, 1.0f);

    // 2) PZ[z] = x[b] @ P[h]^T -> hi plane only
    tc_gemm<false,false,false,false,3><<<dim3(4, 16, 16), blk, SM_NT>>>(
        xhi, xlo, Ph, nullptr, PZhi, nullptr,
        Dd, Dd, Dd, Dd,
        Hh, Bb, (size_t)Tt * Dd,
        1,  Hh, (size_t)Dd * Dd,
        (size_t)Tt * Dd, nullptr, nullptr, 1.0f);

    // 3) S[z] = tril(QZ[z] @ x[b]^T) / sqrt(D) -> split planes
    tc_gemm<true,false,false,false,1><<<dim3(16, 16, 16), blk, SM_NT>>>(
        QZhi, QZlo, xhi, nullptr, Shi, Slo,
        Dd, Dd, Dd, Tt,
        1, Bb * Hh, (size_t)Tt * Dd,
        Hh, Bb,     (size_t)Tt * Dd,
        (size_t)Tt * Tt, nullptr, nullptr, inv_sqrt_d);

    // 4) Yp[z] = S[z] @ PZ[z]  (NN, causal K-limit) -> fp32
    tc_gemm<false,false,true,true,0><<<dim3(4, 16, 16), blk, SM_NN>>>(
        Shi, Slo, PZhi, Yp, nullptr, nullptr,
        Tt, Tt, Dd, Dd,
        1, Bb * Hh, (size_t)Tt * Tt,
        1, Bb * Hh, (size_t)Tt * Dd,
        (size_t)Tt * Dd, nullptr, nullptr, 1.0f);

    // 5) Z = LayerNorm(mean_h(Yp) + x) -> fp32 + split planes
    ln_reduce<<<Bb * Tt, 128>>>(Yp, x, gamma, beta, Z, Zhi, Zlo);

    // 6) M1 = relu(Z @ W1^T + b1) -> split planes
    tc_gemm<false,true,false,false,1><<<dim3(8, 32, 1), blk, SM_NT>>>(
        Zhi, Zlo, W1h, nullptr, M1hi, M1lo,
        Dd, Dd, Dd, 2 * Dd,
        1, 1, 0, 1, 1, 0, 0, b1, nullptr, 1.0f);

    // 7) Z2 = Z + (M1 @ W2^T + b2) -> split planes
    tc_gemm<false,false,false,false,1><<<dim3(4, 32, 1), blk, SM_NT>>>(
        M1hi, M1lo, W2h, nullptr, Z2hi, Z2lo,
        2 * Dd, 2 * Dd, 2 * Dd, Dd,
        1, 1, 0, 1, 1, 0, 0, b2, Z, 1.0f);

    // 8) out = Z2 @ Wp^T + bp -> fp32
    tc_gemm<false,false,false,false,0><<<dim3(4, 32, 1), blk, SM_NT>>>(
        Z2hi, Z2lo, Wph, out, nullptr, nullptr,
        Dd, Dd, Dd, Dd,
        1, 1, 0, 1, 1, 0, 0, bp, nullptr, 1.0f);
}